// round 16
// baseline (speedup 1.0000x reference)
#include <cuda_runtime.h>
#include <cstdint>

// Problem constants (fixed by the dataset)
#define NMAX 50000
#define FF   4
#define TT   12
#define FT   48   // F*T contiguous floats per node in x layout [N,F,T]
#define CC   32
#define HOR  12
#define CAP  128  // bucket capacity per node (deg ~ Poisson(16); overflow P ~ 1e-60)

#define TPB    512              // threads per block
#define BLKSM  3                // co-resident blocks per SM
#define WPB    (TPB / 32)       // warps per block
#define CHUNK  2                // nodes per work-steal grab

typedef unsigned long long u64;

// Scratch (allocation-free: __device__ globals)
__device__ int   g_cnt[NMAX];
__device__ float g_dis[NMAX];
__device__ float g_y[(size_t)NMAX * FT];         // y_i = dis_i * x_i
__device__ __align__(16) int2 g_bucket[(size_t)NMAX * CAP];   // {row, float_bits(w)}
__device__ float g_Az[FF * CC];   // scaled by -log2(e)
__device__ float g_Ah[FF * CC];   // scaled by -2*log2(e)
__device__ float g_cz[CC];        // scaled by -log2(e)
__device__ float g_ch[CC];        // scaled by -2*log2(e)
__device__ float g_probs[TT];
__device__ int   g_is64;
__device__ int   g_nodectr;       // P3 work-stealing cursor (reset each launch)

// Software grid barrier state (persistent kernel)
__device__ unsigned g_bar_arrive = 0;
__device__ volatile unsigned g_bar_gen = 0;

__device__ __forceinline__ void grid_barrier(int nblocks) {
    __syncthreads();
    if (threadIdx.x == 0) {
        __threadfence();
        unsigned gen = g_bar_gen;
        if (atomicAdd(&g_bar_arrive, 1u) == (unsigned)(nblocks - 1)) {
            atomicExch(&g_bar_arrive, 0u);
            __threadfence();
            g_bar_gen = gen + 1;
        } else {
            while (g_bar_gen == gen) { __nanosleep(64); }
            __threadfence();
        }
    }
    __syncthreads();
}

__device__ __forceinline__ int edge_idx(const void* ei, size_t pos, int is64) {
    if (is64) return (int)((const long long*)ei)[pos];
    return ((const int*)ei)[pos];
}

// ---- packed f32x2 helpers (sm_103a) ----
__device__ __forceinline__ u64 pk2(float lo, float hi) {
    u64 r; asm("mov.b64 %0, {%1,%2};" : "=l"(r) : "f"(lo), "f"(hi)); return r;
}
__device__ __forceinline__ void upk2(u64 v, float& lo, float& hi) {
    asm("mov.b64 {%0,%1}, %2;" : "=f"(lo), "=f"(hi) : "l"(v));
}
__device__ __forceinline__ u64 fma2(u64 a, u64 b, u64 c) {
    u64 d; asm("fma.rn.f32x2 %0, %1, %2, %3;" : "=l"(d) : "l"(a), "l"(b), "l"(c)); return d;
}
__device__ __forceinline__ u64 add2(u64 a, u64 b) {
    u64 d; asm("add.rn.f32x2 %0, %1, %2;" : "=l"(d) : "l"(a), "l"(b)); return d;
}
__device__ __forceinline__ u64 mul2(u64 a, u64 b) {
    u64 d; asm("mul.rn.f32x2 %0, %1, %2;" : "=l"(d) : "l"(a), "l"(b)); return d;
}
__device__ __forceinline__ float ex2a(float x) {
    float y; asm("ex2.approx.f32 %0, %1;" : "=f"(y) : "f"(x)); return y;
}
__device__ __forceinline__ float rcpa(float x) {
    float y; asm("rcp.approx.f32 %0, %1;" : "=f"(y) : "f"(x)); return y;
}

// ---------------------------------------------------------------------------
// ONE persistent kernel; phases separated by software grid barriers.
__global__ __launch_bounds__(TPB, BLKSM)
void k_mega(const float* __restrict__ x, const void* __restrict__ ei,
            const float* __restrict__ w, const float* __restrict__ att,
            const float* __restrict__ Wz, const float* __restrict__ bz,
            const float* __restrict__ Wlz, const float* __restrict__ blz,
            const float* __restrict__ Wh, const float* __restrict__ bh,
            const float* __restrict__ Wlh, const float* __restrict__ blh,
            const float* __restrict__ Wout, const float* __restrict__ bout,
            float* __restrict__ out, int N, int E, int nblocks)
{
    __shared__ float sAz[FF * CC], sAh[FF * CC];
    __shared__ float scz[CC], sch[CC], sprobs[TT];
    __shared__ float sWout[CC * HOR], sbout[HOR];
    __shared__ float sAf[WPB][FT];    // per-warp af[t*4+f]
    __shared__ float sH[WPB][CC];     // per-warp Hacc per channel

    const int tid = threadIdx.x;
    const int bid = blockIdx.x;
    const int gsz = nblocks * TPB;
    const int g   = bid * TPB + tid;
    const float L2E = 1.4426950408889634f;

    // ---- P0: zero counts; block 0: dtype detect + matrix fusion + softmax
    for (int i = g; i < N; i += gsz) g_cnt[i] = 0;
    if (g == 0) g_nodectr = 0;
    if (bid == 0) {
        if (tid < 32) {
            const int* e32 = (const int*)ei;
            int nz = (e32[2 * (2 * tid) + 1] != 0) | (e32[2 * (2 * tid + 1) + 1] != 0);
            unsigned any = __ballot_sync(0xffffffffu, nz);
            if (tid == 0) g_is64 = (any == 0) ? 1 : 0;
        } else if (tid < 160) {
            int t2 = tid - 32;
            int f = t2 >> 5;        // 0..3
            int c = t2 & 31;        // 0..31
            float az = 0.0f, ah = 0.0f;
            #pragma unroll
            for (int k = 0; k < CC; k++) {
                az += Wz[f * CC + k] * Wlz[k * CC + c];
                ah += Wh[f * CC + k] * Wlh[k * CC + c];
            }
            g_Az[f * CC + c] = -L2E * az;          // prescaled: nz = log2(e^{-zp})
            g_Ah[f * CC + c] = -2.0f * L2E * ah;   // prescaled: nh = log2(e^{-2hp})
            if (f == 0) {
                float cz = blz[c], ch = blh[c];
                #pragma unroll
                for (int k = 0; k < CC; k++) {
                    cz += bz[k] * Wlz[k * CC + c];
                    ch += bh[k] * Wlh[k * CC + c];
                }
                g_cz[c] = -L2E * cz;
                g_ch[c] = -2.0f * L2E * ch;
            }
        } else if (tid == 160) {
            float m = att[0];
            for (int t = 1; t < TT; t++) m = fmaxf(m, att[t]);
            float e[TT]; float s = 0.0f;
            for (int t = 0; t < TT; t++) { e[t] = __expf(att[t] - m); s += e[t]; }
            float inv = 1.0f / s;
            for (int t = 0; t < TT; t++) g_probs[t] = e[t] * inv;
        }
    }
    grid_barrier(nblocks);

    const int is64 = g_is64;
    const int lane = tid & 31;
    const int warp0 = g >> 5;
    const int nwarps = gsz >> 5;

    // ---- P1: single-pass bucket fill: {row, w} appended per destination col
    if (!is64) {
        // int32 fast path: 2 edges per thread, vector loads
        const int* e32 = (const int*)ei;
        int Ep = E & ~1;
        for (int e = g * 2; e < Ep; e += gsz * 2) {
            int2   rr = *(const int2*)(e32 + e);
            int2   cc = *(const int2*)(e32 + E + e);
            float2 ww = *(const float2*)(w + e);
            if ((unsigned)rr.x < (unsigned)N && (unsigned)cc.x < (unsigned)N) {
                int slot = atomicAdd(&g_cnt[cc.x], 1);
                if (slot < CAP)
                    g_bucket[(size_t)cc.x * CAP + slot] = make_int2(rr.x, __float_as_int(ww.x));
            }
            if ((unsigned)rr.y < (unsigned)N && (unsigned)cc.y < (unsigned)N) {
                int slot = atomicAdd(&g_cnt[cc.y], 1);
                if (slot < CAP)
                    g_bucket[(size_t)cc.y * CAP + slot] = make_int2(rr.y, __float_as_int(ww.y));
            }
        }
        if ((E & 1) && g == 0) {
            int e = E - 1;
            int r = e32[e], c = e32[E + e];
            if ((unsigned)r < (unsigned)N && (unsigned)c < (unsigned)N) {
                int slot = atomicAdd(&g_cnt[c], 1);
                if (slot < CAP)
                    g_bucket[(size_t)c * CAP + slot] = make_int2(r, __float_as_int(w[e]));
            }
        }
    } else {
        for (int e = g; e < E; e += gsz) {
            int r = edge_idx(ei, (size_t)e, is64);
            int c = edge_idx(ei, (size_t)E + e, is64);
            if ((unsigned)r >= (unsigned)N || (unsigned)c >= (unsigned)N) continue;
            int slot = atomicAdd(&g_cnt[c], 1);
            if (slot < CAP)
                g_bucket[(size_t)c * CAP + slot] = make_int2(r, __float_as_int(w[e]));
        }
    }
    grid_barrier(nblocks);

    // ---- P2: warp-per-node: deg (coalesced + butterfly), dis, y = dis*x
    for (int i = warp0; i < N; i += nwarps) {
        int m = min(g_cnt[i], CAP);
        const int2* b = g_bucket + (size_t)i * CAP;
        float s = 0.0f;
        for (int k = lane; k < m; k += 32) s += __int_as_float(b[k].y);
        s += __shfl_xor_sync(0xffffffffu, s, 1);
        s += __shfl_xor_sync(0xffffffffu, s, 2);
        s += __shfl_xor_sync(0xffffffffu, s, 4);
        s += __shfl_xor_sync(0xffffffffu, s, 8);
        s += __shfl_xor_sync(0xffffffffu, s, 16);
        float dc = rsqrtf(s + 1.0f);
        if (lane == 0) g_dis[i] = dc;
        const float* xi = x + (size_t)i * FT;
        float* yi = g_y + (size_t)i * FT;
        yi[lane] = dc * xi[lane];
        if (lane < 16) yi[lane + 32] = dc * xi[lane + 32];
    }
    grid_barrier(nblocks);

    // ---- P3: work-stealing gather + GRU epilogue, warp per node
    for (int k = tid; k < FF * CC; k += TPB) { sAz[k] = g_Az[k]; sAh[k] = g_Ah[k]; }
    for (int k = tid; k < CC; k += TPB)      { scz[k] = g_cz[k]; sch[k] = g_ch[k]; }
    for (int k = tid; k < TT; k += TPB)      sprobs[k] = g_probs[k];
    for (int k = tid; k < CC * HOR; k += TPB) sWout[k] = Wout[k];
    for (int k = tid; k < HOR; k += TPB)      sbout[k] = bout[k];
    __syncthreads();

    const int wid = tid >> 5;     // warp within block (smem row)
    const int c   = lane;         // GRU channel for epilogue
    const bool act = (lane < 24); // lanes 0..23 hold the 48-float row as pairs
    const unsigned FULL = 0xffffffffu;

    // ---- grab first chunk + prologue prefetch
    int base = 0;
    if (lane == 0) base = atomicAdd(&g_nodectr, CHUNK);
    base = __shfl_sync(FULL, base, 0);

    int  endP = 0;
    int2 beP  = make_int2(0, 0);
    float disP = 0.0f;
    u64  qsP  = 0ull;
    if (base < N) {
        endP = g_cnt[base];
        beP  = __ldg(g_bucket + (size_t)base * CAP + lane);
        disP = g_dis[base];
        if (act) qsP = __ldg((const u64*)(g_y + (size_t)base * FT) + lane);
    }

    while (base < N) {
        int lim = min(base + CHUNK, N);
        for (int i = base; i < lim; i++) {
            int   end = min(endP, CAP);
            int2  be  = beP;
            float dcv = disP;
            u64   qs  = qsP;

            // lane l holds y floats [2l, 2l+1] => (f=l/6, t=2*(l%6), 2*(l%6)+1)
            u64 acca = 0ull, accb = 0ull;

            int m = min(32, end);
            int j = 0;
            for (; j + 2 <= m; j += 2) {
                int   r0 = __shfl_sync(FULL, be.x, j);
                float w0 = __int_as_float(__shfl_sync(FULL, be.y, j));
                int   r1 = __shfl_sync(FULL, be.x, j + 1);
                float w1 = __int_as_float(__shfl_sync(FULL, be.y, j + 1));
                if (act) {
                    u64 q0 = __ldg((const u64*)(g_y + (size_t)r0 * FT) + lane);
                    u64 q1 = __ldg((const u64*)(g_y + (size_t)r1 * FT) + lane);
                    acca = fma2(pk2(w0, w0), q0, acca);
                    accb = fma2(pk2(w1, w1), q1, accb);
                }
            }
            if (j < m) {
                int   r0 = __shfl_sync(FULL, be.x, j);
                float w0 = __int_as_float(__shfl_sync(FULL, be.y, j));
                if (act) {
                    u64 q0 = __ldg((const u64*)(g_y + (size_t)r0 * FT) + lane);
                    acca = fma2(pk2(w0, w0), q0, acca);
                }
            }
            // rare: deg > 32
            for (int b2 = 32; b2 < end; b2 += 32) {
                int mm = min(32, end - b2);
                int2 be2 = __ldg(g_bucket + (size_t)i * CAP + b2 + lane);
                for (int jj = 0; jj < mm; jj++) {
                    int   r0 = __shfl_sync(FULL, be2.x, jj);
                    float w0 = __int_as_float(__shfl_sync(FULL, be2.y, jj));
                    if (act) {
                        u64 q0 = __ldg((const u64*)(g_y + (size_t)r0 * FT) + lane);
                        acca = fma2(pk2(w0, w0), q0, acca);
                    }
                }
            }

            // ---- next node: within chunk, or steal a new chunk now so the
            //      atomic + prefetch latency hides under this node's epilogue
            int inext;
            if (i + 1 < lim) {
                inext = i + 1;
            } else {
                if (lane == 0) base = atomicAdd(&g_nodectr, CHUNK);
                base = __shfl_sync(FULL, base, 0);
                inext = (base < N) ? base : -1;
            }
            if (inext >= 0) {
                endP = g_cnt[inext];
                beP  = __ldg(g_bucket + (size_t)inext * CAP + lane);
                disP = g_dis[inext];
                if (act) qsP = __ldg((const u64*)(g_y + (size_t)inext * FT) + lane);
            }

            // self + factored dis[col]:  xa = dc * (S + y_i), publish to sAf
            if (act) {
                u64 acc = mul2(add2(add2(acca, accb), qs), pk2(dcv, dcv));
                float alo, ahi;
                upk2(acc, alo, ahi);
                int f  = lane / 6;
                int t0 = 2 * (lane % 6);
                sAf[wid][t0 * 4 + f]       = alo;
                sAf[wid][(t0 + 1) * 4 + f] = ahi;
            }
            __syncwarp();

            // GRU epilogue: lane owns ONE channel; t processed in pairs.
            // nz = log2(e^{-zp}) via prescaled constants; ez=2^nz, eh=2^nh
            // (1-sigmoid(zp))*tanh(hp) = ez*(1-eh)/((1+ez)(1+eh))
            // pair: p0*n0/d0 + p1*n1/d1 = (p0n0d1 + p1n1d0)*rcp(d0*d1)
            float Hacc = 0.0f;
            #pragma unroll
            for (int tp = 0; tp < 6; tp++) {
                float4 af0 = *(const float4*)&sAf[wid][(2 * tp) * 4];
                float4 af1 = *(const float4*)&sAf[wid][(2 * tp + 1) * 4];
                float nz0 = scz[c] + af0.x * sAz[0 * CC + c] + af0.y * sAz[1 * CC + c]
                                   + af0.z * sAz[2 * CC + c] + af0.w * sAz[3 * CC + c];
                float nh0 = sch[c] + af0.x * sAh[0 * CC + c] + af0.y * sAh[1 * CC + c]
                                   + af0.z * sAh[2 * CC + c] + af0.w * sAh[3 * CC + c];
                float nz1 = scz[c] + af1.x * sAz[0 * CC + c] + af1.y * sAz[1 * CC + c]
                                   + af1.z * sAz[2 * CC + c] + af1.w * sAz[3 * CC + c];
                float nh1 = sch[c] + af1.x * sAh[0 * CC + c] + af1.y * sAh[1 * CC + c]
                                   + af1.z * sAh[2 * CC + c] + af1.w * sAh[3 * CC + c];
                float ez0 = ex2a(nz0), eh0 = ex2a(nh0);
                float ez1 = ex2a(nz1), eh1 = ex2a(nh1);
                float num0 = fmaf(ez0, -eh0, ez0);       // ez*(1-eh)
                float num1 = fmaf(ez1, -eh1, ez1);
                float den0 = (1.0f + ez0) * (1.0f + eh0);
                float den1 = (1.0f + ez1) * (1.0f + eh1);
                float nsum = fmaf(sprobs[2 * tp] * num0, den1,
                                  sprobs[2 * tp + 1] * num1 * den0);
                Hacc = fmaf(nsum, rcpa(den0 * den1), Hacc);  // Hn=(1-Z)*Ht
            }
            sH[wid][c] = fmaxf(Hacc, 0.0f);
            __syncwarp();

            // projection: lanes 0..11 -> ch 0..15, lanes 12..23 -> ch 16..31
            float part = 0.0f;
            int jj2 = (lane < 12) ? lane : lane - 12;
            int k0 = (lane < 12) ? 0 : 16;
            if (lane < 24) {
                #pragma unroll
                for (int k = 0; k < 16; k++)
                    part += sH[wid][k0 + k] * sWout[(k0 + k) * HOR + jj2];
            }
            float other = __shfl_down_sync(FULL, part, 12);
            if (lane < HOR)
                out[(size_t)i * HOR + lane] = part + other + sbout[lane];
            __syncwarp();
        }
    }
}

// ---------------------------------------------------------------------------
extern "C" void kernel_launch(void* const* d_in, const int* in_sizes, int n_in,
                              void* d_out, int out_size) {
    const float* x    = (const float*)d_in[0];
    const void*  ei   = d_in[1];
    const float* w    = (const float*)d_in[2];
    const float* att  = (const float*)d_in[3];
    const float* Wz   = (const float*)d_in[4];
    const float* bz   = (const float*)d_in[5];
    const float* Wlz  = (const float*)d_in[6];
    const float* blz  = (const float*)d_in[7];
    // d_in[8..11] = Wr, br, Wlr, blr  -- dead (H0 stays zero in the reference)
    const float* Wh   = (const float*)d_in[12];
    const float* bh   = (const float*)d_in[13];
    const float* Wlh  = (const float*)d_in[14];
    const float* blh  = (const float*)d_in[15];
    const float* Wout = (const float*)d_in[16];
    const float* bout = (const float*)d_in[17];
    float*       out  = (float*)d_out;

    int E = in_sizes[2];          // edge_weight element count
    int N = in_sizes[0] / FT;     // x is N*F*T

    int dev = 0, sms = 148;
    cudaGetDevice(&dev);
    cudaDeviceGetAttribute(&sms, cudaDevAttrMultiProcessorCount, dev);

    int nblocks = sms * BLKSM;
    k_mega<<<nblocks, TPB>>>(x, ei, w, att, Wz, bz, Wlz, blz,
                             Wh, bh, Wlh, blh, Wout, bout, out, N, E, nblocks);
}